// round 11
// baseline (speedup 1.0000x reference)
#include <cuda_runtime.h>
#include <math.h>

#define N_G   1024
#define SCALE 1.0f
#define DXC   (2.0f / 31.0f)
#define QCUT  60.0f                // dropped terms < e^-30 of dominant: negligible
#define CANDCAP 512
#define GRID_TOTAL 128

__device__ float d_img[N_G * 75];  // (N, 3, 5, 5): c*25 + kx*5 + ky
__device__ unsigned g_arrive;      // zero-init; reset at end of every run
__device__ unsigned g_depart;

__device__ __forceinline__ float tanha(float x) {
    float y;
    asm("tanh.approx.f32 %0, %1;" : "=f"(y) : "f"(x));
    return y;
}

// ---- dynamic smem layout (float offsets), all regions 16B-aligned ----
#define OFF_SWC   0        // 3750 (+2)
#define OFF_SWE   3752     // 180
#define OFF_SWL   3932     // 6400
#define OFF_SBC   10332    // 50 (+2)
#define OFF_SBE   10384    // 30 (+2)
#define OFF_SBL   10416    // 80
#define OFF_SHW   10496    // 160
#define OFF_SHB   10656    // 2 (+2)
#define OFF_PRMT  10660    // 8 warps * 24 = 192  (prmT[w][p][4g])
#define OFF_WSLAB 10852    // 8 warps * 944 (imgT 304 | hT 320 | h2T 320)
#define SMEM_FLTS 18404    // 73616 B -> 2-3 blocks/SM capacity >= 128 blocks

// Phase-A scratch aliases into the warp-slab region (phase B writes it only
// after the grid barrier).
#define PA_CA    10852     // 512 float4
#define PA_CB    12900     // 512 float4
#define PA_MISC  14948     // wcnt8 + wbase8 + total

__global__ void __launch_bounds__(256) k_all(
    const float* __restrict__ means,  const float* __restrict__ u,
    const float* __restrict__ scaling,const float* __restrict__ transform,
    const float* __restrict__ conv_w, const float* __restrict__ conv_b,
    const float* __restrict__ emb_w,  const float* __restrict__ emb_b,
    const float* __restrict__ lin1_w, const float* __restrict__ lin1_b,
    const float* __restrict__ sol_w,  const float* __restrict__ sol_b,
    const float* __restrict__ tr_w,   const float* __restrict__ tr_b,
    const float* __restrict__ sc_w,   const float* __restrict__ sc_b,
    const float* __restrict__ tf_w,   const float* __restrict__ tf_b,
    float* __restrict__ out)
{
    extern __shared__ float sm[];
    const int b    = blockIdx.x;
    const int tid  = threadIdx.x;
    const int w    = tid >> 5;
    const int lane = tid & 31;

    const int m  = b & 3;               // network
    const int g0 = (b >> 2) * 32;       // phase-B gaussian base (32/block)
    const int od = (m == 1 || m == 2) ? 2 : 1;

    // ============ pre-barrier loads (overlap with phase A) ============
    {
        const float4* lw4 = (const float4*)(lin1_w + m * 6400);
        float4* sl4 = (float4*)(sm + OFF_SWL);
        for (int idx = tid; idx < 1600; idx += 256) sl4[idx] = lw4[idx];
        const float2* cw2 = (const float2*)(conv_w + m * 3750);
        float2* sc2 = (float2*)(sm + OFF_SWC);
        for (int idx = tid; idx < 1875; idx += 256) sc2[idx] = cw2[idx];
        const float2* ew2 = (const float2*)(emb_w + m * 180);
        float2* se2 = (float2*)(sm + OFF_SWE);
        if (tid < 90) se2[tid] = ew2[tid];
    }
    if (tid < 50) sm[OFF_SBC + tid] = conv_b[m * 50 + tid];
    if (tid >= 64 && tid < 94)  sm[OFF_SBE + tid - 64] = emb_b[m * 30 + (tid - 64)];
    if (tid >= 96 && tid < 176) sm[OFF_SBL + tid - 96] = lin1_b[m * 80 + (tid - 96)];
    {
        const float* hw; const float* hb;
        if      (m == 0) { hw = sol_w; hb = sol_b; }
        else if (m == 1) { hw = tr_w;  hb = tr_b;  }
        else if (m == 2) { hw = sc_w;  hb = sc_b;  }
        else             { hw = tf_w;  hb = tf_b;  }
        for (int idx = tid; idx < 80 * od; idx += 256) sm[OFF_SHW + idx] = hw[idx];
        if (tid < od) sm[OFF_SHB + tid] = hb[tid];
    }
    // prmT[w][p][gi] for this block's 32 phase-B gaussians
    if (tid < 192) {
        int g = tid / 6, p = tid - g * 6;
        int i = g0 + g;
        float v;
        if      (p == 0) v = means[2 * i];
        else if (p == 1) v = means[2 * i + 1];
        else if (p == 2) v = u[i];
        else if (p == 3) v = scaling[2 * i];
        else if (p == 4) v = scaling[2 * i + 1];
        else             v = transform[i];
        sm[OFF_PRMT + (g >> 2) * 24 + p * 4 + (g & 3)] = v;
    }

    // =================== PHASE A: sampling for gaussians [8b, 8b+8) ==========
    {
        float4* cA = (float4*)(sm + PA_CA);
        float4* cB = (float4*)(sm + PA_CB);
        int* s_wcnt  = (int*)(sm + PA_MISC);
        int* s_wbase = (int*)(sm + PA_MISC + 8);
        int* s_total = (int*)(sm + PA_MISC + 16);

        if (tid == 0) *s_total = 0;
        __syncthreads();

        const int i0 = b * 8;
        float bminx = 1e30f, bmaxx = -1e30f, bminy = 1e30f, bmaxy = -1e30f;
        #pragma unroll
        for (int g = 0; g < 8; ++g) {
            float mx = means[2 * (i0 + g)], my = means[2 * (i0 + g) + 1];
            bminx = fminf(bminx, mx); bmaxx = fmaxf(bmaxx, mx);
            bminy = fminf(bminy, my); bmaxy = fmaxf(bmaxy, my);
        }
        bminx -= 2.0f * DXC; bmaxx += 2.0f * DXC;
        bminy -= 2.0f * DXC; bmaxy += 2.0f * DXC;

        for (int c = 0; c < N_G / 256; ++c) {
            int j = c * 256 + tid;
            float mx = means[2 * j], my = means[2 * j + 1];
            float s0 = scaling[2 * j], s1 = scaling[2 * j + 1], t = transform[j];
            float A = s0 * s0, B = s0 * t, C = t * t + s1 * s1;
            float inv = 1.0f / (A * C - B * B);
            float ca =  C * inv, cb = -B * inv, cc = A * inv;
            float h = 0.5f * (A + C);
            float r = sqrtf(0.25f * (A - C) * (A - C) + B * B);
            float r2max = QCUT * (h + r);
            float ddx = fmaxf(fmaxf(bminx - mx, mx - bmaxx), 0.0f);
            float ddy = fmaxf(fmaxf(bminy - my, my - bmaxy), 0.0f);
            bool pred = (ddx * ddx + ddy * ddy) <= r2max;
            unsigned bm = __ballot_sync(0xffffffffu, pred);
            if (lane == 0) s_wcnt[w] = __popc(bm);
            __syncthreads();
            if (tid == 0) {
                int acc = *s_total;
                for (int w2 = 0; w2 < 8; ++w2) { s_wbase[w2] = acc; acc += s_wcnt[w2]; }
                *s_total = acc;
            }
            __syncthreads();
            if (pred) {
                int idx = s_wbase[w] + __popc(bm & ((1u << lane) - 1u));
                if (idx < CANDCAP) {
                    cA[idx] = make_float4(mx, my, r2max, u[j]);
                    cB[idx] = make_float4(ca, cb, cc, ca + cc);
                }
            }
            __syncthreads();
        }
        int cnt = *s_total;
        if (cnt > CANDCAP) cnt = CANDCAP;

        // evaluate 200 samples (threads 0..199), with in-loop distance prune
        if (tid < 200) {
            const int i  = i0 + tid / 25;
            const int k  = tid % 25;
            const int kx = k / 5, ky = k % 5;
            const float sx = means[2 * i]     + (float)(kx - 2) * DXC;
            const float sy = means[2 * i + 1] + (float)(ky - 2) * DXC;
            float us = 0.0f, pd = 0.0f;
            for (int t2 = 0; t2 < cnt; ++t2) {
                float4 A = cA[t2];
                float dx = sx - A.x;
                float dy = sy - A.y;
                float d2 = dx * dx + dy * dy;
                if (d2 <= A.z) {
                    float4 Bv = cB[t2];
                    float Cd0 = Bv.x * dx + Bv.y * dy;
                    float Cd1 = Bv.y * dx + Bv.z * dy;
                    float q   = dx * Cd0 + dy * Cd1;
                    float wv  = __expf(-0.5f * q) * A.w;
                    us += wv;
                    pd += wv * (Cd0 * Cd0 + Cd1 * Cd1 - Bv.w);
                }
            }
            float maskv = (fabsf(sx) < SCALE && fabsf(sy) < SCALE) ? 1.0f : 0.0f;
            d_img[i * 75 +  0 + k] = us;
            d_img[i * 75 + 25 + k] = pd;
            d_img[i * 75 + 50 + k] = maskv;
        }
    }

    // =================== GRID BARRIER (co-residency guaranteed) ==============
    __threadfence();
    __syncthreads();
    if (tid == 0) {
        atomicAdd(&g_arrive, 1u);
        while (atomicAdd(&g_arrive, 0u) < GRID_TOTAL) { }
    }
    __syncthreads();

    // =================== PHASE B: warp-autonomous networks ===================
    float* swc  = sm + OFF_SWC;
    float* swe  = sm + OFF_SWE;
    float* swl  = sm + OFF_SWL;
    float* sbc  = sm + OFF_SBC;
    float* sbe  = sm + OFF_SBE;
    float* sbl  = sm + OFF_SBL;
    float* shw  = sm + OFF_SHW;
    float* shb  = sm + OFF_SHB;
    float* prmT = sm + OFF_PRMT + w * 24;
    float* slab = sm + OFF_WSLAB + w * 944;
    float* imgT = slab;          // [kk*4 + gi], kk<75
    float* hT   = slab + 304;    // [row*4 + gi], row<80
    float* h2T  = slab + 624;    // [q*4 + gi],  q<80

    // load this block's 32 gaussian images into per-warp transposed slabs
    for (int idx = tid; idx < 2400; idx += 256) {
        int g = idx / 75, kk = idx - g * 75;
        sm[OFF_WSLAB + (g >> 2) * 944 + kk * 4 + (g & 3)] = d_img[(g0 + g) * 75 + kk];
    }
    __syncthreads();   // last block-wide barrier: imgT ready

    // ---- conv: lanes 0..24 handle o = 2*lane, 2*lane+1 for 4 gaussians ----
    if (lane < 25) {
        int o0 = lane * 2, o1 = o0 + 1;
        float bb0 = sbc[o0], bb1 = sbc[o1];
        float a0[4] = {bb0, bb0, bb0, bb0};
        float a1[4] = {bb1, bb1, bb1, bb1};
        const float* w0r = &swc[o0 * 75];
        const float* w1r = &swc[o1 * 75];
        #pragma unroll 5
        for (int kk = 0; kk < 75; ++kk) {
            float w0 = w0r[kk], w1 = w1r[kk];
            float4 v = *(const float4*)&imgT[kk * 4];
            a0[0] = fmaf(w0, v.x, a0[0]); a1[0] = fmaf(w1, v.x, a1[0]);
            a0[1] = fmaf(w0, v.y, a0[1]); a1[1] = fmaf(w1, v.y, a1[1]);
            a0[2] = fmaf(w0, v.z, a0[2]); a1[2] = fmaf(w1, v.z, a1[2]);
            a0[3] = fmaf(w0, v.w, a0[3]); a1[3] = fmaf(w1, v.w, a1[3]);
        }
        *(float4*)&hT[o0 * 4] = make_float4(tanha(a0[0]), tanha(a0[1]), tanha(a0[2]), tanha(a0[3]));
        *(float4*)&hT[o1 * 4] = make_float4(tanha(a1[0]), tanha(a1[1]), tanha(a1[2]), tanha(a1[3]));
    }
    // ---- embedding: lanes 0..29 handle q = lane ----
    if (lane < 30) {
        int q = lane;
        float be = sbe[q];
        float a[4] = {be, be, be, be};
        #pragma unroll
        for (int p = 0; p < 6; ++p) {
            float wv = swe[p * 30 + q];
            float4 pv = *(const float4*)&prmT[p * 4];
            a[0] = fmaf(wv, pv.x, a[0]); a[1] = fmaf(wv, pv.y, a[1]);
            a[2] = fmaf(wv, pv.z, a[2]); a[3] = fmaf(wv, pv.w, a[3]);
        }
        *(float4*)&hT[(50 + q) * 4] = make_float4(tanha(a[0]), tanha(a[1]), tanha(a[2]), tanha(a[3]));
    }
    __syncwarp();

    // ---- lin1 80x80: lane handles q = lane, lane+32, (lane+64 for lane<16) ----
    {
        float l0[4], l1[4], l2[4];
        float b0 = sbl[lane], b1 = sbl[lane + 32];
        float b2 = (lane < 16) ? sbl[lane + 64] : 0.0f;
        #pragma unroll
        for (int g = 0; g < 4; ++g) { l0[g] = b0; l1[g] = b1; l2[g] = b2; }
        #pragma unroll 4
        for (int p = 0; p < 80; ++p) {
            float4 hv = *(const float4*)&hT[p * 4];
            float w0 = swl[p * 80 + lane];
            float w1 = swl[p * 80 + lane + 32];
            l0[0] = fmaf(w0, hv.x, l0[0]); l0[1] = fmaf(w0, hv.y, l0[1]);
            l0[2] = fmaf(w0, hv.z, l0[2]); l0[3] = fmaf(w0, hv.w, l0[3]);
            l1[0] = fmaf(w1, hv.x, l1[0]); l1[1] = fmaf(w1, hv.y, l1[1]);
            l1[2] = fmaf(w1, hv.z, l1[2]); l1[3] = fmaf(w1, hv.w, l1[3]);
            if (lane < 16) {
                float w2 = swl[p * 80 + lane + 64];
                l2[0] = fmaf(w2, hv.x, l2[0]); l2[1] = fmaf(w2, hv.y, l2[1]);
                l2[2] = fmaf(w2, hv.z, l2[2]); l2[3] = fmaf(w2, hv.w, l2[3]);
            }
        }
        *(float4*)&h2T[lane * 4]        = make_float4(tanha(l0[0]), tanha(l0[1]), tanha(l0[2]), tanha(l0[3]));
        *(float4*)&h2T[(lane + 32) * 4] = make_float4(tanha(l1[0]), tanha(l1[1]), tanha(l1[2]), tanha(l1[3]));
        if (lane < 16)
            *(float4*)&h2T[(lane + 64) * 4] = make_float4(tanha(l2[0]), tanha(l2[1]), tanha(l2[2]), tanha(l2[3]));
    }
    __syncwarp();

    // ---- head: 4 p-chunks of 20 x (od*4) outputs, shfl reduction ----
    {
        int chunk = lane >> 3;
        int r     = lane & 7;
        int d     = r >> 2;
        int gi    = r & 3;
        float acc = 0.0f;
        if (d < od) {
            int pbase = chunk * 20;
            #pragma unroll 5
            for (int p = 0; p < 20; ++p)
                acc = fmaf(h2T[(pbase + p) * 4 + gi], shw[(pbase + p) * od + d], acc);
        }
        acc += __shfl_down_sync(0xffffffffu, acc, 16);
        acc += __shfl_down_sync(0xffffffffu, acc, 8);
        if (lane < 8) {
            int dd = lane >> 2, gg = lane & 3;
            if (dd < od) {
                float v = shb[dd] + acc;
                int i = g0 + w * 4 + gg;
                if      (m == 0) out[i * 6 + 0]      = prmT[2 * 4 + gg]        + v;
                else if (m == 1) out[i * 6 + 1 + dd] = prmT[dd * 4 + gg]       + v;
                else if (m == 2) out[i * 6 + 3 + dd] = prmT[(3 + dd) * 4 + gg] * __expf(v);
                else             out[i * 6 + 5]      = prmT[5 * 4 + gg]        + v;
            }
        }
    }

    // ---- barrier counter reset (last block out restores initial state) ----
    __syncthreads();
    if (tid == 0) {
        unsigned d = atomicAdd(&g_depart, 1u) + 1u;
        if (d == GRID_TOTAL) { g_arrive = 0u; g_depart = 0u; __threadfence(); }
    }
}

// ---------------------------------------------------------------------------
extern "C" void kernel_launch(void* const* d_in, const int* in_sizes, int n_in,
                              void* d_out, int out_size)
{
    const float* means     = (const float*)d_in[0];
    const float* u         = (const float*)d_in[1];
    const float* scaling   = (const float*)d_in[2];
    const float* transform = (const float*)d_in[3];
    const float* conv_w    = (const float*)d_in[4];
    const float* conv_b    = (const float*)d_in[5];
    const float* emb_w     = (const float*)d_in[6];
    const float* emb_b     = (const float*)d_in[7];
    const float* lin1_w    = (const float*)d_in[8];
    const float* lin1_b    = (const float*)d_in[9];
    const float* sol_w     = (const float*)d_in[10];
    const float* sol_b     = (const float*)d_in[11];
    const float* tr_w      = (const float*)d_in[12];
    const float* tr_b      = (const float*)d_in[13];
    const float* sc_w      = (const float*)d_in[14];
    const float* sc_b      = (const float*)d_in[15];
    const float* tf_w      = (const float*)d_in[16];
    const float* tf_b      = (const float*)d_in[17];
    float* out             = (float*)d_out;

    static int smem_set = 0;
    if (!smem_set) {
        cudaFuncSetAttribute(k_all, cudaFuncAttributeMaxDynamicSharedMemorySize,
                             SMEM_FLTS * (int)sizeof(float));
        smem_set = 1;
    }

    k_all<<<GRID_TOTAL, 256, SMEM_FLTS * sizeof(float)>>>(
        means, u, scaling, transform,
        conv_w, conv_b, emb_w, emb_b, lin1_w, lin1_b,
        sol_w, sol_b, tr_w, tr_b, sc_w, sc_b, tf_w, tf_b, out);
}

// round 12
// speedup vs baseline: 1.1761x; 1.1761x over previous
#include <cuda_runtime.h>
#include <math.h>

#define N_G   1024
#define SCALE 1.0f
#define DXC   (2.0f / 31.0f)
#define QCUT  60.0f                // dropped terms < e^-30 of dominant: negligible
#define CANDCAP 384
#define GRID_TOTAL 256

__device__ float d_img[N_G * 75];  // (N, 3, 5, 5): c*25 + kx*5 + ky
__device__ unsigned g_arrive;      // zero-init; reset at end of every run
__device__ unsigned g_depart;

__device__ __forceinline__ float tanha(float x) {
    float y;
    asm("tanh.approx.f32 %0, %1;" : "=f"(y) : "f"(x));
    return y;
}

// ---- dynamic smem layout (float offsets), all regions 16B-aligned ----
#define OFF_SWC   0        // 3750 (+2)
#define OFF_SWE   3752     // 180
#define OFF_SWL   3932     // 6400
#define OFF_SBC   10332    // 50 (+2)
#define OFF_SBE   10384    // 30 (+2)
#define OFF_SBL   10416    // 80
#define OFF_SHW   10496    // 160
#define OFF_SHB   10656    // 2 (+2)
#define OFF_PRMT  10660    // 8 warps * 12 = 96 (prmT[w][p][2g])
#define OFF_WSLAB 10756    // 8 warps * 472 (imgT 152 | hT 160 | h2T 160)
#define SMEM_FLTS 14532    // 58128 B -> 3 blocks/SM, capacity 444 >= 256

// Phase-A scratch aliases into the warp-slab region (phase B writes it only
// after the grid barrier).
#define PA_CA    10756     // 384 float4 = 1536 floats
#define PA_CB    12292     // 384 float4 = 1536 floats
#define PA_MISC  13828     // wcnt8 + wbase8 + total (20)
#define PA_PUS   13848     // 100
#define PA_PPD   13948     // 100

__global__ void __launch_bounds__(256) k_all(
    const float* __restrict__ means,  const float* __restrict__ u,
    const float* __restrict__ scaling,const float* __restrict__ transform,
    const float* __restrict__ conv_w, const float* __restrict__ conv_b,
    const float* __restrict__ emb_w,  const float* __restrict__ emb_b,
    const float* __restrict__ lin1_w, const float* __restrict__ lin1_b,
    const float* __restrict__ sol_w,  const float* __restrict__ sol_b,
    const float* __restrict__ tr_w,   const float* __restrict__ tr_b,
    const float* __restrict__ sc_w,   const float* __restrict__ sc_b,
    const float* __restrict__ tf_w,   const float* __restrict__ tf_b,
    float* __restrict__ out)
{
    extern __shared__ float sm[];
    const int b    = blockIdx.x;
    const int tid  = threadIdx.x;
    const int w    = tid >> 5;
    const int lane = tid & 31;

    const int m  = b & 3;               // network
    const int g0 = (b >> 2) * 16;       // phase-B gaussian base (16/block)
    const int od = (m == 1 || m == 2) ? 2 : 1;

    // ============ pre-barrier loads (overlap with phase A) ============
    {
        const float4* lw4 = (const float4*)(lin1_w + m * 6400);
        float4* sl4 = (float4*)(sm + OFF_SWL);
        for (int idx = tid; idx < 1600; idx += 256) sl4[idx] = lw4[idx];
        const float2* cw2 = (const float2*)(conv_w + m * 3750);
        float2* sc2 = (float2*)(sm + OFF_SWC);
        for (int idx = tid; idx < 1875; idx += 256) sc2[idx] = cw2[idx];
        const float2* ew2 = (const float2*)(emb_w + m * 180);
        float2* se2 = (float2*)(sm + OFF_SWE);
        if (tid < 90) se2[tid] = ew2[tid];
    }
    if (tid < 50) sm[OFF_SBC + tid] = conv_b[m * 50 + tid];
    if (tid >= 64 && tid < 94)  sm[OFF_SBE + tid - 64] = emb_b[m * 30 + (tid - 64)];
    if (tid >= 96 && tid < 176) sm[OFF_SBL + tid - 96] = lin1_b[m * 80 + (tid - 96)];
    {
        const float* hw; const float* hb;
        if      (m == 0) { hw = sol_w; hb = sol_b; }
        else if (m == 1) { hw = tr_w;  hb = tr_b;  }
        else if (m == 2) { hw = sc_w;  hb = sc_b;  }
        else             { hw = tf_w;  hb = tf_b;  }
        for (int idx = tid; idx < 80 * od; idx += 256) sm[OFF_SHW + idx] = hw[idx];
        if (tid < od) sm[OFF_SHB + tid] = hb[tid];
    }
    // prmT[w][p][gi] for this block's 16 phase-B gaussians (2 per warp)
    if (tid < 96) {
        int g = tid / 6, p = tid - g * 6;
        int i = g0 + g;
        float v;
        if      (p == 0) v = means[2 * i];
        else if (p == 1) v = means[2 * i + 1];
        else if (p == 2) v = u[i];
        else if (p == 3) v = scaling[2 * i];
        else if (p == 4) v = scaling[2 * i + 1];
        else             v = transform[i];
        sm[OFF_PRMT + (g >> 1) * 12 + p * 2 + (g & 1)] = v;
    }

    // =================== PHASE A: sampling for gaussians [4b, 4b+4) ==========
    {
        float4* cA = (float4*)(sm + PA_CA);
        float4* cB = (float4*)(sm + PA_CB);
        int* s_wcnt  = (int*)(sm + PA_MISC);
        int* s_wbase = (int*)(sm + PA_MISC + 8);
        int* s_total = (int*)(sm + PA_MISC + 16);
        float* pus = sm + PA_PUS;
        float* ppd = sm + PA_PPD;

        if (tid == 0) *s_total = 0;
        __syncthreads();

        const int i0 = b * 4;
        float bminx = 1e30f, bmaxx = -1e30f, bminy = 1e30f, bmaxy = -1e30f;
        #pragma unroll
        for (int g = 0; g < 4; ++g) {
            float mx = means[2 * (i0 + g)], my = means[2 * (i0 + g) + 1];
            bminx = fminf(bminx, mx); bmaxx = fmaxf(bmaxx, mx);
            bminy = fminf(bminy, my); bmaxy = fmaxf(bmaxy, my);
        }
        bminx -= 2.0f * DXC; bmaxx += 2.0f * DXC;
        bminy -= 2.0f * DXC; bmaxy += 2.0f * DXC;

        for (int c = 0; c < N_G / 256; ++c) {
            int j = c * 256 + tid;
            float mx = means[2 * j], my = means[2 * j + 1];
            float s0 = scaling[2 * j], s1 = scaling[2 * j + 1], t = transform[j];
            float A = s0 * s0, B = s0 * t, C = t * t + s1 * s1;
            float inv = 1.0f / (A * C - B * B);
            float ca =  C * inv, cb = -B * inv, cc = A * inv;
            float h = 0.5f * (A + C);
            float r = sqrtf(0.25f * (A - C) * (A - C) + B * B);
            float r2max = QCUT * (h + r);
            float ddx = fmaxf(fmaxf(bminx - mx, mx - bmaxx), 0.0f);
            float ddy = fmaxf(fmaxf(bminy - my, my - bmaxy), 0.0f);
            bool pred = (ddx * ddx + ddy * ddy) <= r2max;
            unsigned bm = __ballot_sync(0xffffffffu, pred);
            if (lane == 0) s_wcnt[w] = __popc(bm);
            __syncthreads();
            if (tid == 0) {
                int acc = *s_total;
                for (int w2 = 0; w2 < 8; ++w2) { s_wbase[w2] = acc; acc += s_wcnt[w2]; }
                *s_total = acc;
            }
            __syncthreads();
            if (pred) {
                int idx = s_wbase[w] + __popc(bm & ((1u << lane) - 1u));
                if (idx < CANDCAP) {
                    cA[idx] = make_float4(mx, my, r2max, u[j]);
                    cB[idx] = make_float4(ca, cb, cc, ca + cc);
                }
            }
            __syncthreads();
        }
        int cnt = *s_total;
        if (cnt > CANDCAP) cnt = CANDCAP;

        // evaluate 100 samples on 200 threads (2 threads/sample, even/odd split)
        float us = 0.0f, pd = 0.0f;
        float sx = 0.0f, sy = 0.0f;
        int   sl = 0;
        if (tid < 200) {
            int half = tid / 100;
            sl = tid - half * 100;
            const int s  = b * 100 + sl;
            const int i  = s / 25;
            const int k  = s % 25;
            const int kx = k / 5, ky = k % 5;
            sx = means[2 * i]     + (float)(kx - 2) * DXC;
            sy = means[2 * i + 1] + (float)(ky - 2) * DXC;
            for (int t2 = half; t2 < cnt; t2 += 2) {
                float4 A  = cA[t2];
                float4 Bv = cB[t2];
                float dx = sx - A.x;
                float dy = sy - A.y;
                float Cd0 = Bv.x * dx + Bv.y * dy;
                float Cd1 = Bv.y * dx + Bv.z * dy;
                float q   = dx * Cd0 + dy * Cd1;
                float wv  = __expf(-0.5f * q) * A.w;
                us += wv;
                pd += wv * (Cd0 * Cd0 + Cd1 * Cd1 - Bv.w);
            }
            if (half == 1) { pus[sl] = us; ppd[sl] = pd; }
        }
        __syncthreads();
        if (tid < 100) {
            us += pus[sl];
            pd += ppd[sl];
            const int s = b * 100 + sl;
            const int i = s / 25;
            const int k = s % 25;
            float maskv = (fabsf(sx) < SCALE && fabsf(sy) < SCALE) ? 1.0f : 0.0f;
            d_img[i * 75 +  0 + k] = us;
            d_img[i * 75 + 25 + k] = pd;
            d_img[i * 75 + 50 + k] = maskv;
        }
    }

    // =================== GRID BARRIER (co-residency guaranteed) ==============
    __threadfence();
    __syncthreads();
    if (tid == 0) {
        atomicAdd(&g_arrive, 1u);
        while (atomicAdd(&g_arrive, 0u) < GRID_TOTAL) { }
    }
    __syncthreads();

    // =================== PHASE B: warp-autonomous networks (2 g / warp) ======
    float* swc  = sm + OFF_SWC;
    float* swe  = sm + OFF_SWE;
    float* swl  = sm + OFF_SWL;
    float* sbc  = sm + OFF_SBC;
    float* sbe  = sm + OFF_SBE;
    float* sbl  = sm + OFF_SBL;
    float* shw  = sm + OFF_SHW;
    float* shb  = sm + OFF_SHB;
    float* prmT = sm + OFF_PRMT + w * 12;
    float* slab = sm + OFF_WSLAB + w * 472;
    float* imgT = slab;          // [kk*2 + gi], kk<75
    float* hT   = slab + 152;    // [row*2 + gi], row<80
    float* h2T  = slab + 312;    // [q*2 + gi],  q<80

    // load this block's 16 gaussian images into per-warp transposed slabs
    for (int idx = tid; idx < 1200; idx += 256) {
        int g = idx / 75, kk = idx - g * 75;
        sm[OFF_WSLAB + (g >> 1) * 472 + kk * 2 + (g & 1)] = d_img[(g0 + g) * 75 + kk];
    }
    __syncthreads();   // last block-wide barrier: imgT ready

    // ---- conv: lanes 0..24 handle o = 2*lane, 2*lane+1 for 2 gaussians ----
    if (lane < 25) {
        int o0 = lane * 2, o1 = o0 + 1;
        float bb0 = sbc[o0], bb1 = sbc[o1];
        float a00 = bb0, a01 = bb0, a10 = bb1, a11 = bb1;
        const float* w0r = &swc[o0 * 75];
        const float* w1r = &swc[o1 * 75];
        #pragma unroll 5
        for (int kk = 0; kk < 75; ++kk) {
            float w0 = w0r[kk], w1 = w1r[kk];
            float2 v = *(const float2*)&imgT[kk * 2];
            a00 = fmaf(w0, v.x, a00); a01 = fmaf(w0, v.y, a01);
            a10 = fmaf(w1, v.x, a10); a11 = fmaf(w1, v.y, a11);
        }
        *(float2*)&hT[o0 * 2] = make_float2(tanha(a00), tanha(a01));
        *(float2*)&hT[o1 * 2] = make_float2(tanha(a10), tanha(a11));
    }
    // ---- embedding: lanes 0..29 handle q = lane for 2 gaussians ----
    if (lane < 30) {
        int q = lane;
        float be = sbe[q];
        float a0 = be, a1 = be;
        #pragma unroll
        for (int p = 0; p < 6; ++p) {
            float wv = swe[p * 30 + q];
            float2 pv = *(const float2*)&prmT[p * 2];
            a0 = fmaf(wv, pv.x, a0);
            a1 = fmaf(wv, pv.y, a1);
        }
        *(float2*)&hT[(50 + q) * 2] = make_float2(tanha(a0), tanha(a1));
    }
    __syncwarp();

    // ---- lin1 80x80: lane handles q = lane, lane+32, (lane+64 for lane<16) ----
    {
        float l00 = sbl[lane],      l01 = l00;
        float l10 = sbl[lane + 32], l11 = l10;
        float l20 = (lane < 16) ? sbl[lane + 64] : 0.0f, l21 = l20;
        #pragma unroll 4
        for (int p = 0; p < 80; ++p) {
            float2 hv = *(const float2*)&hT[p * 2];
            float w0 = swl[p * 80 + lane];
            float w1 = swl[p * 80 + lane + 32];
            l00 = fmaf(w0, hv.x, l00); l01 = fmaf(w0, hv.y, l01);
            l10 = fmaf(w1, hv.x, l10); l11 = fmaf(w1, hv.y, l11);
            if (lane < 16) {
                float w2 = swl[p * 80 + lane + 64];
                l20 = fmaf(w2, hv.x, l20); l21 = fmaf(w2, hv.y, l21);
            }
        }
        *(float2*)&h2T[lane * 2]        = make_float2(tanha(l00), tanha(l01));
        *(float2*)&h2T[(lane + 32) * 2] = make_float2(tanha(l10), tanha(l11));
        if (lane < 16)
            *(float2*)&h2T[(lane + 64) * 2] = make_float2(tanha(l20), tanha(l21));
    }
    __syncwarp();

    // ---- head: lanes 0..15 = chunk(4) x d(2) x g(2); shfl reduce chunks ----
    {
        int chunk = lane >> 2;          // 0..7 (only 0..3 used)
        int d     = (lane >> 1) & 1;
        int gi    = lane & 1;
        float acc = 0.0f;
        if (lane < 16 && d < od) {
            int pbase = chunk * 20;
            #pragma unroll 5
            for (int p = 0; p < 20; ++p)
                acc = fmaf(h2T[(pbase + p) * 2 + gi], shw[(pbase + p) * od + d], acc);
        }
        acc += __shfl_down_sync(0xffffffffu, acc, 8);
        acc += __shfl_down_sync(0xffffffffu, acc, 4);
        if (lane < 4) {
            int dd = lane >> 1, gg = lane & 1;
            if (dd < od) {
                float v = shb[dd] + acc;
                int i = g0 + w * 2 + gg;
                if      (m == 0) out[i * 6 + 0]      = prmT[2 * 2 + gg]        + v;
                else if (m == 1) out[i * 6 + 1 + dd] = prmT[dd * 2 + gg]       + v;
                else if (m == 2) out[i * 6 + 3 + dd] = prmT[(3 + dd) * 2 + gg] * __expf(v);
                else             out[i * 6 + 5]      = prmT[5 * 2 + gg]        + v;
            }
        }
    }

    // ---- barrier counter reset (last block out restores initial state) ----
    __syncthreads();
    if (tid == 0) {
        unsigned d = atomicAdd(&g_depart, 1u) + 1u;
        if (d == GRID_TOTAL) { g_arrive = 0u; g_depart = 0u; __threadfence(); }
    }
}

// ---------------------------------------------------------------------------
extern "C" void kernel_launch(void* const* d_in, const int* in_sizes, int n_in,
                              void* d_out, int out_size)
{
    const float* means     = (const float*)d_in[0];
    const float* u         = (const float*)d_in[1];
    const float* scaling   = (const float*)d_in[2];
    const float* transform = (const float*)d_in[3];
    const float* conv_w    = (const float*)d_in[4];
    const float* conv_b    = (const float*)d_in[5];
    const float* emb_w     = (const float*)d_in[6];
    const float* emb_b     = (const float*)d_in[7];
    const float* lin1_w    = (const float*)d_in[8];
    const float* lin1_b    = (const float*)d_in[9];
    const float* sol_w     = (const float*)d_in[10];
    const float* sol_b     = (const float*)d_in[11];
    const float* tr_w      = (const float*)d_in[12];
    const float* tr_b      = (const float*)d_in[13];
    const float* sc_w      = (const float*)d_in[14];
    const float* sc_b      = (const float*)d_in[15];
    const float* tf_w      = (const float*)d_in[16];
    const float* tf_b      = (const float*)d_in[17];
    float* out             = (float*)d_out;

    static int smem_set = 0;
    if (!smem_set) {
        cudaFuncSetAttribute(k_all, cudaFuncAttributeMaxDynamicSharedMemorySize,
                             SMEM_FLTS * (int)sizeof(float));
        smem_set = 1;
    }

    k_all<<<GRID_TOTAL, 256, SMEM_FLTS * sizeof(float)>>>(
        means, u, scaling, transform,
        conv_w, conv_b, emb_w, emb_b, lin1_w, lin1_b,
        sol_w, sol_b, tr_w, tr_b, sc_w, sc_b, tf_w, tf_b, out);
}